// round 7
// baseline (speedup 1.0000x reference)
#include <cuda_runtime.h>
#include <math.h>

#define Bn 32
#define Sn 512
#define Hn 768
#define FDn 64
#define Pn 30
#define PPn 32
#define NROWS (Bn*Sn)    // 16384

typedef unsigned long long u64;

__device__ __forceinline__ void fma2(u64 &d, u64 a, u64 b) {
    asm("fma.rn.f32x2 %0, %1, %2, %0;" : "+l"(d) : "l"(a), "l"(b));
}
__device__ __forceinline__ void add2(u64 &d, u64 a) {
    asm("add.rn.f32x2 %0, %0, %1;" : "+l"(d) : "l"(a));
}
__device__ __forceinline__ u64 rep2(float a) {
    u64 r; asm("mov.b64 %0, {%1, %1};" : "=l"(r) : "f"(a)); return r;
}
__device__ __forceinline__ float2 unpk(u64 v) {
    float2 f; asm("mov.b64 {%0, %1}, %2;" : "=f"(f.x), "=f"(f.y) : "l"(v)); return f;
}

// ------------------ scratch ------------------
__device__ float g_WT [Hn * PPn];        // W_t^T [k][p], p padded to 32
__device__ float g_WaT[FDn * PPn];       // W_a^T [k][p]
__device__ float g_pt [2 * NROWS * 32];  // text K-split partials (4.2 MB)
__device__ float g_text [NROWS * PPn];   // [row][p]
__device__ float g_audio[NROWS * PPn];   // [row][p]
__device__ float g_part[256];
__device__ float g_raw0[Bn * Sn];
__device__ float g_avp[Bn * 16 * Hn];

// ------------------ K0: transpose weights (R2 verbatim) ------------------
__global__ void k_prep(const float* __restrict__ Wt, const float* __restrict__ Wa) {
    int e = blockIdx.x * 256 + threadIdx.x;
    if (blockIdx.x < 96) {                 // 768*32
        int p = e & 31, k = e >> 5;
        g_WT[k * 32 + p] = (p < Pn) ? Wt[p * Hn + k] : 0.f;
    } else {
        e -= 96 * 256;                     // 64*32
        int p = e & 31, k = e >> 5;
        g_WaT[k * 32 + p] = (p < Pn) ? Wa[p * FDn + k] : 0.f;
    }
}

// ------------------ K1: text projection (R2 geometry + f32x2 + K-split 2) ------------------
// grid (128 row-tiles, 2 k-split), block 256. Thread: rows rg*4+i, p pg*4..pg*4+3.
__global__ __launch_bounds__(256) void k_proj(const float* __restrict__ hs) {
    __shared__ __align__(16) float sA[128 * 68];
    __shared__ __align__(16) float sW[64 * 36];
    int tid = threadIdx.x;
    int pg = tid & 7, rg = tid >> 3;
    int row0 = blockIdx.x * 128;
    int kbase = blockIdx.y * 384;
    const float4* hs4 = (const float4*)hs;
    const float4* gW4 = (const float4*)g_WT;

    u64 acc2[4][2];
    #pragma unroll
    for (int i = 0; i < 4; i++) { acc2[i][0] = 0ull; acc2[i][1] = 0ull; }

    for (int cc = 0; cc < 6; cc++) {
        int kb = kbase + cc * 64;
        __syncthreads();
        #pragma unroll
        for (int q = 0; q < 8; q++) {          // A: 128 rows x 64 k
            int e = tid + 256 * q;
            int r = e >> 4, c = e & 15;
            float4 v = hs4[(size_t)(row0 + r) * 192 + (kb >> 2) + c];
            *(float4*)&sA[r * 68 + c * 4] = v;
        }
        #pragma unroll
        for (int q = 0; q < 2; q++) {          // W: 64 x 32
            int e = tid + 256 * q;
            int k = e >> 3, pc = e & 7;
            float4 v = gW4[(kb + k) * 8 + pc];
            *(float4*)&sW[k * 36 + pc * 4] = v;
        }
        __syncthreads();
        #pragma unroll
        for (int kk = 0; kk < 16; kk++) {
            int k = kk * 4;
            float4 A0 = *(float4*)&sA[(rg * 4 + 0) * 68 + k];
            float4 A1 = *(float4*)&sA[(rg * 4 + 1) * 68 + k];
            float4 A2 = *(float4*)&sA[(rg * 4 + 2) * 68 + k];
            float4 A3 = *(float4*)&sA[(rg * 4 + 3) * 68 + k];
            #pragma unroll
            for (int kq = 0; kq < 4; kq++) {
                u64 w01 = *(const u64*)&sW[(k + kq) * 36 + pg * 4];
                u64 w23 = *(const u64*)&sW[(k + kq) * 36 + pg * 4 + 2];
                float a0 = (kq == 0) ? A0.x : (kq == 1) ? A0.y : (kq == 2) ? A0.z : A0.w;
                float a1 = (kq == 0) ? A1.x : (kq == 1) ? A1.y : (kq == 2) ? A1.z : A1.w;
                float a2 = (kq == 0) ? A2.x : (kq == 1) ? A2.y : (kq == 2) ? A2.z : A2.w;
                float a3 = (kq == 0) ? A3.x : (kq == 1) ? A3.y : (kq == 2) ? A3.z : A3.w;
                u64 r0 = rep2(a0), r1 = rep2(a1), r2 = rep2(a2), r3 = rep2(a3);
                fma2(acc2[0][0], r0, w01); fma2(acc2[0][1], r0, w23);
                fma2(acc2[1][0], r1, w01); fma2(acc2[1][1], r1, w23);
                fma2(acc2[2][0], r2, w01); fma2(acc2[2][1], r2, w23);
                fma2(acc2[3][0], r3, w01); fma2(acc2[3][1], r3, w23);
            }
        }
    }
    #pragma unroll
    for (int i = 0; i < 4; i++) {
        u64* d = (u64*)&g_pt[(size_t)blockIdx.y * (NROWS * 32) +
                             (size_t)(row0 + rg * 4 + i) * 32 + pg * 4];
        d[0] = acc2[i][0]; d[1] = acc2[i][1];
    }
}

// ------------------ K2: merge partials + sumsq + audio GEMM ------------------
// grid 256 (64-row tiles), block 256
__global__ __launch_bounds__(256) void k_merge(const float* __restrict__ ad) {
    __shared__ __align__(16) float sA[64 * 68];
    __shared__ __align__(16) float sW[64 * 36];
    __shared__ float red[256];
    int tid = threadIdx.x;
    int pg = tid & 7, rg = tid >> 3;          // audio: rows rg*2+i, p pg*4..
    int row0 = blockIdx.x * 64;

    // ---- text merge + sumsq ----
    size_t base0 = (size_t)row0 * 32;         // float offset; 64*32=2048 floats = 1024 u64
    float sumsq = 0.f;
    #pragma unroll
    for (int q = 0; q < 4; q++) {
        int idx = tid + 256 * q;              // u64 index
        u64 t  = *(const u64*)&g_pt[base0 + (size_t)idx * 2];
        u64 t2 = *(const u64*)&g_pt[(size_t)(NROWS * 32) + base0 + (size_t)idx * 2];
        add2(t, t2);
        float2 f = unpk(t);
        sumsq += f.x * f.x + f.y * f.y;
        *(u64*)&g_text[base0 + (size_t)idx * 2] = t;
    }
    red[tid] = sumsq;

    // ---- audio tiles ----
    #pragma unroll
    for (int q = 0; q < 4; q++) {             // ad: 64 rows x 16 float4
        int e = tid + 256 * q;
        int r = e >> 4, c = e & 15;
        float4 v = ((const float4*)ad)[(size_t)(row0 + r) * 16 + c];
        *(float4*)&sA[r * 68 + c * 4] = v;
    }
    #pragma unroll
    for (int q = 0; q < 2; q++) {             // WaT: 64 x 32
        int e = tid + 256 * q;
        int k = e >> 3, pc = e & 7;
        float4 v = ((const float4*)g_WaT)[k * 8 + pc];
        *(float4*)&sW[k * 36 + pc * 4] = v;
    }
    __syncthreads();

    u64 acc2[2][2];
    acc2[0][0] = acc2[0][1] = acc2[1][0] = acc2[1][1] = 0ull;
    #pragma unroll 8
    for (int k = 0; k < 64; k++) {
        u64 w01 = *(const u64*)&sW[k * 36 + pg * 4];
        u64 w23 = *(const u64*)&sW[k * 36 + pg * 4 + 2];
        u64 a0 = rep2(sA[(rg * 2 + 0) * 68 + k]);
        u64 a1 = rep2(sA[(rg * 2 + 1) * 68 + k]);
        fma2(acc2[0][0], a0, w01); fma2(acc2[0][1], a0, w23);
        fma2(acc2[1][0], a1, w01); fma2(acc2[1][1], a1, w23);
    }
    #pragma unroll
    for (int i = 0; i < 2; i++) {
        u64* d = (u64*)&g_audio[(size_t)(row0 + rg * 2 + i) * 32 + pg * 4];
        d[0] = acc2[i][0]; d[1] = acc2[i][1];
    }

    // ---- sumsq block reduce ----
    __syncthreads();
    for (int s = 128; s > 0; s >>= 1) {
        if (tid < s) red[tid] += red[tid + s];
        __syncthreads();
    }
    if (tid == 0) g_part[blockIdx.x] = red[0];
}

// ------------------ K3: score matrices (R2 verbatim + norm prologue) ------------------
// grid (36 upper-tri tile pairs, 32 b), 256 threads, 64x64 tiles, 4x4 micro.
__global__ __launch_bounds__(256) void k_scores(const float* __restrict__ twp,
                                                const float* __restrict__ awp,
                                                const float* __restrict__ fbp,
                                                float* __restrict__ out_ta,
                                                float* __restrict__ out_fa) {
    __shared__ float sTs[64 * 33], sTt[64 * 33], sAs[64 * 33], sAt[64 * 33];
    __shared__ float scs;
    int x = blockIdx.x, si = 0;
    while (x >= 8 - si) { x -= 8 - si; si++; }
    int ti = si + x;
    int b = blockIdx.y;
    int s0 = si * 64, t0 = ti * 64;
    int tid = threadIdx.x;

    // norm-scale prologue (sum of 256 partials)
    if (tid < 32) {
        float v = 0.f;
        #pragma unroll
        for (int j = 0; j < 8; j++) v += g_part[tid + 32 * j];
        #pragma unroll
        for (int o = 16; o > 0; o >>= 1) v += __shfl_xor_sync(0xffffffff, v, o);
        if (tid == 0) scs = rsqrtf(v);
    }

    const float* gts = g_text  + (size_t)(b * Sn + s0) * PPn;
    const float* gtt = g_text  + (size_t)(b * Sn + t0) * PPn;
    const float* gas = g_audio + (size_t)(b * Sn + s0) * PPn;
    const float* gat = g_audio + (size_t)(b * Sn + t0) * PPn;
    for (int e = tid; e < 64 * 32; e += 256) {
        int r = e >> 5, p = e & 31;
        sTs[r * 33 + p] = gts[r * 32 + p];
        sTt[r * 33 + p] = gtt[r * 32 + p];
        sAs[r * 33 + p] = gas[r * 32 + p];
        sAt[r * 33 + p] = gat[r * 32 + p];
    }
    __syncthreads();

    int tx = tid & 15, ty = tid >> 4;
    float st[16], sa[16];
    #pragma unroll
    for (int i = 0; i < 16; i++) { st[i] = 0.f; sa[i] = 0.f; }

    const float* ps = sTs + (ty * 4) * 33;
    const float* pt = sTt + (tx * 4) * 33;
    const float* qs = sAs + (ty * 4) * 33;
    const float* qt = sAt + (tx * 4) * 33;

    #pragma unroll 6
    for (int p = 0; p < Pn; p++) {
        float a0 = ps[p], a1 = ps[33 + p], a2 = ps[66 + p], a3 = ps[99 + p];
        float b0 = pt[p], b1 = pt[33 + p], b2 = pt[66 + p], b3 = pt[99 + p];
        st[0]  += a0 * b0; st[1]  += a0 * b1; st[2]  += a0 * b2; st[3]  += a0 * b3;
        st[4]  += a1 * b0; st[5]  += a1 * b1; st[6]  += a1 * b2; st[7]  += a1 * b3;
        st[8]  += a2 * b0; st[9]  += a2 * b1; st[10] += a2 * b2; st[11] += a2 * b3;
        st[12] += a3 * b0; st[13] += a3 * b1; st[14] += a3 * b2; st[15] += a3 * b3;
        float c0 = qs[p], c1 = qs[33 + p], c2 = qs[66 + p], c3 = qs[99 + p];
        float d0 = qt[p], d1 = qt[33 + p], d2 = qt[66 + p], d3 = qt[99 + p];
        sa[0]  += c0 * d0; sa[1]  += c0 * d1; sa[2]  += c0 * d2; sa[3]  += c0 * d3;
        sa[4]  += c1 * d0; sa[5]  += c1 * d1; sa[6]  += c1 * d2; sa[7]  += c1 * d3;
        sa[8]  += c2 * d0; sa[9]  += c2 * d1; sa[10] += c2 * d2; sa[11] += c2 * d3;
        sa[12] += c3 * d0; sa[13] += c3 * d1; sa[14] += c3 * d2; sa[15] += c3 * d3;
    }

    float cs = scs;
    float tw = twp[0], aw = awp[0], fb = fbp[0];
    float ta[16], fa[16];
    float rw[4];
    #pragma unroll
    for (int i = 0; i < 4; i++)
        #pragma unroll
        for (int j = 0; j < 4; j++) {
            float t_ = fmaxf(st[i * 4 + j] * cs, 0.f);
            float a_ = fmaxf(sa[i * 4 + j], 0.f);
            float r_ = tw * t_ + aw * a_ + fb;
            ta[i * 4 + j] = t_;
            fa[i * 4 + j] = fmaxf(r_, 0.f);
            if (i == 0) rw[j] = r_;
        }

    #pragma unroll
    for (int i = 0; i < 4; i++) {
        int s = s0 + ty * 4 + i;
        size_t base = ((size_t)(b * Sn + s)) * Sn + t0 + tx * 4;
        *(float4*)(out_ta + base) = make_float4(ta[i*4], ta[i*4+1], ta[i*4+2], ta[i*4+3]);
        *(float4*)(out_fa + base) = make_float4(fa[i*4], fa[i*4+1], fa[i*4+2], fa[i*4+3]);
    }
    if (si == 0 && ty == 0)
        *(float4*)(g_raw0 + b * Sn + t0 + tx * 4) =
            make_float4(rw[0], rw[1], rw[2], rw[3]);

    if (si != ti) {
        #pragma unroll
        for (int j = 0; j < 4; j++) {
            int t = t0 + tx * 4 + j;
            size_t base = ((size_t)(b * Sn + t)) * Sn + s0 + ty * 4;
            *(float4*)(out_ta + base) = make_float4(ta[j], ta[4+j], ta[8+j], ta[12+j]);
            *(float4*)(out_fa + base) = make_float4(fa[j], fa[4+j], fa[8+j], fa[12+j]);
        }
    }
}

// ------------------ K4: softmax + AV partials (R6 verbatim) ------------------
__global__ __launch_bounds__(256) void k_softav(const float* __restrict__ hs,
                                                const float* __restrict__ am) {
    __shared__ float sp[Sn];
    __shared__ float red[256];
    int b = blockIdx.x, cy = blockIdx.y, tid = threadIdx.x;
    int t0c = cy * 32;

    float mbase = am[b * Sn];
    float l0 = g_raw0[b * Sn + tid]       + am[b * Sn + tid]       + mbase;
    float l1 = g_raw0[b * Sn + tid + 256] + am[b * Sn + tid + 256] + mbase;
    red[tid] = fmaxf(l0, l1);
    __syncthreads();
    for (int s = 128; s > 0; s >>= 1) {
        if (tid < s) red[tid] = fmaxf(red[tid], red[tid + s]);
        __syncthreads();
    }
    float mx = red[0];
    __syncthreads();
    float e0 = expf(l0 - mx), e1 = expf(l1 - mx);
    red[tid] = e0 + e1;
    __syncthreads();
    for (int s = 128; s > 0; s >>= 1) {
        if (tid < s) red[tid] += red[tid + s];
        __syncthreads();
    }
    float inv = 1.f / red[0];
    __syncthreads();
    sp[tid] = e0 * inv; sp[tid + 256] = e1 * inv;
    __syncthreads();

    if (tid < 192) {
        const float4* hb = (const float4*)(hs + (size_t)b * Sn * Hn);
        float4 acc = make_float4(0.f, 0.f, 0.f, 0.f);
        #pragma unroll 8
        for (int t = 0; t < 32; t++) {
            float p = sp[t0c + t];
            float4 h = hb[(size_t)(t0c + t) * 192 + tid];
            acc.x += p * h.x; acc.y += p * h.y; acc.z += p * h.z; acc.w += p * h.w;
        }
        ((float4*)g_avp)[(size_t)(b * 16 + cy) * 192 + tid] = acc;
    }
}

// ------------------ K5: dense GEMV + layernorm (R6 verbatim) ------------------
__global__ __launch_bounds__(256) void k_denseln(const float* __restrict__ hs,
                                                 const float* __restrict__ Wd,
                                                 const float* __restrict__ bd,
                                                 const float* __restrict__ lw,
                                                 const float* __restrict__ lb,
                                                 float* __restrict__ out0) {
    __shared__ float sx[Hn];
    __shared__ float sh[Hn];
    __shared__ float red[256];
    int b = blockIdx.x, tid = threadIdx.x;
    int w = tid >> 5, lane = tid & 31;

    for (int i = tid; i < Hn; i += 256) {
        float v = hs[(size_t)b * Sn * Hn + i];
        #pragma unroll
        for (int c = 0; c < 16; c++) v += g_avp[(size_t)(b * 16 + c) * Hn + i];
        sx[i] = v;
    }
    __syncthreads();

    const float4* sx4 = (const float4*)sx;
    for (int q = 0; q < 96; q++) {
        int o = w * 96 + q;
        const float4* w4 = (const float4*)(Wd + (size_t)o * Hn);
        float acc = 0.f;
        #pragma unroll
        for (int c = 0; c < 6; c++) {
            float4 wv = w4[c * 32 + lane];
            float4 xv = sx4[c * 32 + lane];
            acc += wv.x * xv.x + wv.y * xv.y + wv.z * xv.z + wv.w * xv.w;
        }
        #pragma unroll
        for (int s = 16; s > 0; s >>= 1)
            acc += __shfl_down_sync(0xffffffff, acc, s);
        if (lane == 0) sh[o] = acc + bd[o];
    }
    __syncthreads();

    float hv[3];
    #pragma unroll
    for (int j = 0; j < 3; j++) hv[j] = sh[tid + 256 * j];
    red[tid] = hv[0] + hv[1] + hv[2];
    __syncthreads();
    for (int s = 128; s > 0; s >>= 1) {
        if (tid < s) red[tid] += red[tid + s];
        __syncthreads();
    }
    float u = red[0] / (float)Hn;
    __syncthreads();
    float vs = 0.f;
    #pragma unroll
    for (int j = 0; j < 3; j++) { float d = hv[j] - u; vs += d * d; }
    red[tid] = vs;
    __syncthreads();
    for (int s = 128; s > 0; s >>= 1) {
        if (tid < s) red[tid] += red[tid + s];
        __syncthreads();
    }
    float rstd = rsqrtf(red[0] / (float)Hn + 1e-12f);
    #pragma unroll
    for (int j = 0; j < 3; j++) {
        int o = tid + 256 * j;
        out0[b * Hn + o] = lw[o] * (hv[j] - u) * rstd + lb[o];
    }
}

// ------------------ launch ------------------
extern "C" void kernel_launch(void* const* d_in, const int* in_sizes, int n_in,
                              void* d_out, int out_size) {
    const float* hs = (const float*)d_in[0];
    const float* ad = (const float*)d_in[1];
    const float* am = (const float*)d_in[2];
    const float* Wt = (const float*)d_in[3];
    const float* Wa = (const float*)d_in[4];
    const float* tw = (const float*)d_in[5];
    const float* aw = (const float*)d_in[6];
    const float* fb = (const float*)d_in[7];
    const float* Wd = (const float*)d_in[8];
    const float* bd = (const float*)d_in[9];
    const float* lw = (const float*)d_in[10];
    const float* lb = (const float*)d_in[11];

    float* out    = (float*)d_out;
    float* out_h0 = out;
    float* out_ta = out + Bn * Hn;
    float* out_fa = out + Bn * Hn + (size_t)Bn * Sn * Sn;

    k_prep<<<104, 256>>>(Wt, Wa);
    k_proj<<<dim3(128, 2), 256>>>(hs);
    k_merge<<<256, 256>>>(ad);
    k_scores<<<dim3(36, 32), 256>>>(tw, aw, fb, out_ta, out_fa);
    k_softav<<<dim3(32, 16), 256>>>(hs, am);
    k_denseln<<<32, 256>>>(hs, Wd, bd, lw, lb, out_h0);
}

// round 8
// speedup vs baseline: 2.1550x; 2.1550x over previous
#include <cuda_runtime.h>
#include <math.h>

#define Bn 32
#define Sn 512
#define Hn 768
#define FDn 64
#define Pn 30
#define NROWS (Bn*Sn)    // 16384

// ------------------ scratch ------------------
__device__ float g_WT [Hn * 32];          // W_t transposed [k][p], zero-padded p
__device__ float g_WaT[FDn * 32];         // W_a transposed [k][p]
__device__ float g_textT [Bn * 32 * Sn];  // [b][p][s]
__device__ float g_audioT[Bn * 32 * Sn];  // [b][p][s]
__device__ float g_part[256];             // block partial sums of text^2
__device__ float g_scale[1];              // 1/norm^2
__device__ float g_raw0[Bn * Sn];
__device__ float g_prob[Bn * Sn];
__device__ float g_avp[Bn * 16 * Hn];
__device__ float g_h[Bn * Hn];

// ------------------ K0: transpose weights ------------------
__global__ void k_prep(const float* __restrict__ Wt, const float* __restrict__ Wa) {
    int e = blockIdx.x * 256 + threadIdx.x;
    if (blockIdx.x < 96) {                 // 768*32 = 24576
        int p = e & 31, k = e >> 5;
        g_WT[k * 32 + p] = (p < Pn) ? Wt[p * Hn + k] : 0.f;
    } else {
        e -= 96 * 256;                     // 64*32 = 2048
        int p = e & 31, k = e >> 5;
        g_WaT[k * 32 + p] = (p < Pn) ? Wa[p * FDn + k] : 0.f;
    }
}

// ------------------ K1: tiled projection GEMM (64-row tiles, 2x4 micro) ------------------
// grid 256, block 256. Block: 64 rows x 32 p. Thread: 2r x 4p.
#define FSTEP(Ai, i)                                                        \
    acc[i][0] += Ai.x*W0.x + Ai.y*W1.x + Ai.z*W2.x + Ai.w*W3.x;             \
    acc[i][1] += Ai.x*W0.y + Ai.y*W1.y + Ai.z*W2.y + Ai.w*W3.y;             \
    acc[i][2] += Ai.x*W0.z + Ai.y*W1.z + Ai.z*W2.z + Ai.w*W3.z;             \
    acc[i][3] += Ai.x*W0.w + Ai.y*W1.w + Ai.z*W2.w + Ai.w*W3.w;

__global__ __launch_bounds__(256) void k_proj(const float* __restrict__ hs,
                                              const float* __restrict__ ad) {
    __shared__ __align__(16) float sA[64 * 68];
    __shared__ __align__(16) float sW[64 * 36];
    int tid = threadIdx.x;
    int pg = tid & 7, rg = tid >> 3;       // p = pg*4+j, r = rg*2+i
    int row0 = blockIdx.x * 64;
    int b = row0 >> 9, s0 = row0 & 511;

    float acc[2][4];
    #pragma unroll
    for (int i = 0; i < 2; i++)
        #pragma unroll
        for (int j = 0; j < 4; j++) acc[i][j] = 0.f;

    // ---- text: K=768 in 12 chunks of 64 ----
    for (int kc = 0; kc < 12; kc++) {
        __syncthreads();
        #pragma unroll
        for (int q = 0; q < 4; q++) {      // A tile 64x64 = 1024 float4
            int e = tid + 256 * q;
            int r = e >> 4, c = e & 15;
            float4 v = ((const float4*)hs)[(size_t)(row0 + r) * 192 + kc * 16 + c];
            *(float4*)&sA[r * 68 + c * 4] = v;
        }
        #pragma unroll
        for (int q = 0; q < 2; q++) {      // W tile 64x32
            int e = tid + 256 * q;
            int k = e >> 3, pc = e & 7;
            float4 v = ((const float4*)g_WT)[(kc * 64 + k) * 8 + pc];
            *(float4*)&sW[k * 36 + pc * 4] = v;
        }
        __syncthreads();
        #pragma unroll
        for (int kk = 0; kk < 16; kk++) {
            int k = kk * 4;
            float4 A0 = *(float4*)&sA[(rg * 2 + 0) * 68 + k];
            float4 A1 = *(float4*)&sA[(rg * 2 + 1) * 68 + k];
            float4 W0 = *(float4*)&sW[(k + 0) * 36 + pg * 4];
            float4 W1 = *(float4*)&sW[(k + 1) * 36 + pg * 4];
            float4 W2 = *(float4*)&sW[(k + 2) * 36 + pg * 4];
            float4 W3 = *(float4*)&sW[(k + 3) * 36 + pg * 4];
            FSTEP(A0, 0) FSTEP(A1, 1)
        }
    }
    float sumsq = 0.f;
    #pragma unroll
    for (int i = 0; i < 2; i++)
        #pragma unroll
        for (int j = 0; j < 4; j++) {
            sumsq += acc[i][j] * acc[i][j];
            int p = pg * 4 + j, s = s0 + rg * 2 + i;
            g_textT[((size_t)(b * 32 + p)) * 512 + s] = acc[i][j];
        }

    // ---- audio: K=64, one chunk ----
    #pragma unroll
    for (int i = 0; i < 2; i++)
        #pragma unroll
        for (int j = 0; j < 4; j++) acc[i][j] = 0.f;
    __syncthreads();
    #pragma unroll
    for (int q = 0; q < 4; q++) {          // A tile 64x64
        int e = tid + 256 * q;
        int r = e >> 4, c = e & 15;
        float4 v = ((const float4*)ad)[(size_t)(row0 + r) * 16 + c];
        *(float4*)&sA[r * 68 + c * 4] = v;
    }
    #pragma unroll
    for (int q = 0; q < 2; q++) {
        int e = tid + 256 * q;
        int k = e >> 3, pc = e & 7;
        float4 v = ((const float4*)g_WaT)[k * 8 + pc];
        *(float4*)&sW[k * 36 + pc * 4] = v;
    }
    __syncthreads();
    #pragma unroll
    for (int kk = 0; kk < 16; kk++) {
        int k = kk * 4;
        float4 A0 = *(float4*)&sA[(rg * 2 + 0) * 68 + k];
        float4 A1 = *(float4*)&sA[(rg * 2 + 1) * 68 + k];
        float4 W0 = *(float4*)&sW[(k + 0) * 36 + pg * 4];
        float4 W1 = *(float4*)&sW[(k + 1) * 36 + pg * 4];
        float4 W2 = *(float4*)&sW[(k + 2) * 36 + pg * 4];
        float4 W3 = *(float4*)&sW[(k + 3) * 36 + pg * 4];
        FSTEP(A0, 0) FSTEP(A1, 1)
    }
    #pragma unroll
    for (int i = 0; i < 2; i++)
        #pragma unroll
        for (int j = 0; j < 4; j++) {
            int p = pg * 4 + j, s = s0 + rg * 2 + i;
            g_audioT[((size_t)(b * 32 + p)) * 512 + s] = acc[i][j];
        }

    // ---- sumsq block reduce (reuse sW) ----
    __syncthreads();
    float* red = sW;
    red[tid] = sumsq;
    __syncthreads();
    for (int s = 128; s > 0; s >>= 1) {
        if (tid < s) red[tid] += red[tid + s];
        __syncthreads();
    }
    if (tid == 0) g_part[blockIdx.x] = red[0];
}

// ------------------ K2: finalize norm scale (256 partials) ------------------
__global__ void k_norm() {
    __shared__ float red[256];
    int tid = threadIdx.x;
    red[tid] = g_part[tid];
    __syncthreads();
    for (int s = 128; s > 0; s >>= 1) {
        if (tid < s) red[tid] += red[tid + s];
        __syncthreads();
    }
    if (tid == 0) g_scale[0] = rsqrtf(red[0]);
}

// ------------------ K3: symmetric score matrices (K_B verbatim) ------------------
// grid (36 upper-tri tile pairs, 32 b), 256 threads, 64x64 tiles, 4x4 micro.
__global__ __launch_bounds__(256) void k_scores(const float* __restrict__ twp,
                                                const float* __restrict__ awp,
                                                const float* __restrict__ fbp,
                                                float* __restrict__ out_ta,
                                                float* __restrict__ out_fa) {
    __shared__ float sTs[32 * 64], sTt[32 * 64], sAs[32 * 64], sAt[32 * 64];
    int x = blockIdx.x, si = 0;
    while (x >= 8 - si) { x -= 8 - si; si++; }
    int ti = si + x;
    int b = blockIdx.y;
    int s0 = si * 64, t0 = ti * 64;
    int tid = threadIdx.x;

    const float4* gT = (const float4*)(g_textT  + (size_t)b * 32 * 512);
    const float4* gA = (const float4*)(g_audioT + (size_t)b * 32 * 512);
    #pragma unroll
    for (int q = 0; q < 2; q++) {
        int e = tid + 256 * q;              // 512 float4 per array
        int p = e >> 4, c = e & 15;
        *(float4*)&sTs[p * 64 + c * 4] = gT[p * 128 + (s0 >> 2) + c];
        *(float4*)&sTt[p * 64 + c * 4] = gT[p * 128 + (t0 >> 2) + c];
        *(float4*)&sAs[p * 64 + c * 4] = gA[p * 128 + (s0 >> 2) + c];
        *(float4*)&sAt[p * 64 + c * 4] = gA[p * 128 + (t0 >> 2) + c];
    }
    __syncthreads();

    int tx = tid & 15, ty = tid >> 4;
    float st[16], sa[16];
    #pragma unroll
    for (int i = 0; i < 16; i++) { st[i] = 0.f; sa[i] = 0.f; }

    #pragma unroll 6
    for (int p = 0; p < Pn; p++) {
        float4 a = *(float4*)&sTs[p * 64 + ty * 4];
        float4 bt = *(float4*)&sTt[p * 64 + tx * 4];
        float4 c = *(float4*)&sAs[p * 64 + ty * 4];
        float4 d = *(float4*)&sAt[p * 64 + tx * 4];
        st[0]  += a.x*bt.x; st[1]  += a.x*bt.y; st[2]  += a.x*bt.z; st[3]  += a.x*bt.w;
        st[4]  += a.y*bt.x; st[5]  += a.y*bt.y; st[6]  += a.y*bt.z; st[7]  += a.y*bt.w;
        st[8]  += a.z*bt.x; st[9]  += a.z*bt.y; st[10] += a.z*bt.z; st[11] += a.z*bt.w;
        st[12] += a.w*bt.x; st[13] += a.w*bt.y; st[14] += a.w*bt.z; st[15] += a.w*bt.w;
        sa[0]  += c.x*d.x;  sa[1]  += c.x*d.y;  sa[2]  += c.x*d.z;  sa[3]  += c.x*d.w;
        sa[4]  += c.y*d.x;  sa[5]  += c.y*d.y;  sa[6]  += c.y*d.z;  sa[7]  += c.y*d.w;
        sa[8]  += c.z*d.x;  sa[9]  += c.z*d.y;  sa[10] += c.z*d.z;  sa[11] += c.z*d.w;
        sa[12] += c.w*d.x;  sa[13] += c.w*d.y;  sa[14] += c.w*d.z;  sa[15] += c.w*d.w;
    }

    float cs = g_scale[0];
    float tw = twp[0], aw = awp[0], fb = fbp[0];
    float ta[16], fa[16];
    float rw[4];
    #pragma unroll
    for (int i = 0; i < 4; i++)
        #pragma unroll
        for (int j = 0; j < 4; j++) {
            float t_ = fmaxf(st[i * 4 + j] * cs, 0.f);
            float a_ = fmaxf(sa[i * 4 + j], 0.f);
            float r_ = tw * t_ + aw * a_ + fb;
            ta[i * 4 + j] = t_;
            fa[i * 4 + j] = fmaxf(r_, 0.f);
            if (i == 0) rw[j] = r_;
        }

    // normal store [s][t]
    #pragma unroll
    for (int i = 0; i < 4; i++) {
        int s = s0 + ty * 4 + i;
        size_t base = ((size_t)(b * Sn + s)) * Sn + t0 + tx * 4;
        *(float4*)(out_ta + base) = make_float4(ta[i*4], ta[i*4+1], ta[i*4+2], ta[i*4+3]);
        *(float4*)(out_fa + base) = make_float4(fa[i*4], fa[i*4+1], fa[i*4+2], fa[i*4+3]);
    }
    if (si == 0 && ty == 0)
        *(float4*)(g_raw0 + b * Sn + t0 + tx * 4) =
            make_float4(rw[0], rw[1], rw[2], rw[3]);

    // mirror store [t][s]
    if (si != ti) {
        #pragma unroll
        for (int j = 0; j < 4; j++) {
            int t = t0 + tx * 4 + j;
            size_t base = ((size_t)(b * Sn + t)) * Sn + s0 + ty * 4;
            *(float4*)(out_ta + base) = make_float4(ta[j], ta[4+j], ta[8+j], ta[12+j]);
            *(float4*)(out_fa + base) = make_float4(fa[j], fa[4+j], fa[8+j], fa[12+j]);
        }
    }
}

// ------------------ K4: softmax probs for s=0 row (K_B verbatim) ------------------
__global__ __launch_bounds__(256) void k_soft(const float* __restrict__ am) {
    __shared__ float red[256];
    int b = blockIdx.x, tid = threadIdx.x;
    float mbase = am[b * Sn];
    float l0 = g_raw0[b * Sn + tid]       + am[b * Sn + tid]       + mbase;
    float l1 = g_raw0[b * Sn + tid + 256] + am[b * Sn + tid + 256] + mbase;

    red[tid] = fmaxf(l0, l1);
    __syncthreads();
    for (int s = 128; s > 0; s >>= 1) {
        if (tid < s) red[tid] = fmaxf(red[tid], red[tid + s]);
        __syncthreads();
    }
    float mx = red[0];
    __syncthreads();
    float e0 = expf(l0 - mx), e1 = expf(l1 - mx);
    red[tid] = e0 + e1;
    __syncthreads();
    for (int s = 128; s > 0; s >>= 1) {
        if (tid < s) red[tid] += red[tid + s];
        __syncthreads();
    }
    float inv = 1.f / red[0];
    g_prob[b * Sn + tid]       = e0 * inv;
    g_prob[b * Sn + tid + 256] = e1 * inv;
}

// ------------------ K5: att @ hidden (K_B verbatim) ------------------
__global__ __launch_bounds__(192) void k_av(const float* __restrict__ hs) {
    __shared__ float sp[32];
    int b = blockIdx.x, cy = blockIdx.y, tid = threadIdx.x;
    int t0 = cy * 32;
    if (tid < 32) sp[tid] = g_prob[b * Sn + t0 + tid];
    __syncthreads();

    const float4* hb = (const float4*)(hs + (size_t)b * Sn * Hn);
    float4 acc = make_float4(0.f, 0.f, 0.f, 0.f);
    #pragma unroll 4
    for (int t = 0; t < 32; t++) {
        float p = sp[t];
        float4 h = hb[(size_t)(t0 + t) * 192 + tid];
        acc.x += p * h.x; acc.y += p * h.y; acc.z += p * h.z; acc.w += p * h.w;
    }
    ((float4*)g_avp)[(size_t)(b * 16 + cy) * 192 + tid] = acc;
}

// ------------------ K6: dense GEMV (K_B verbatim) ------------------
__global__ __launch_bounds__(256) void k_dense(const float* __restrict__ hs,
                                               const float* __restrict__ Wd,
                                               const float* __restrict__ bd) {
    __shared__ float sx[Hn];
    int b = blockIdx.x, oc = blockIdx.y, tid = threadIdx.x;
    int w = tid >> 5, lane = tid & 31;

    for (int i = tid; i < Hn; i += 256) {
        float v = hs[(size_t)b * Sn * Hn + i];
        #pragma unroll
        for (int c = 0; c < 16; c++) v += g_avp[(size_t)(b * 16 + c) * Hn + i];
        sx[i] = v;
    }
    __syncthreads();

    const float4* sx4 = (const float4*)sx;
    #pragma unroll
    for (int q = 0; q < 12; q++) {
        int o = oc * 96 + w * 12 + q;
        const float4* w4 = (const float4*)(Wd + (size_t)o * Hn);
        float acc = 0.f;
        #pragma unroll
        for (int c = 0; c < 6; c++) {
            float4 wv = w4[c * 32 + lane];
            float4 xv = sx4[c * 32 + lane];
            acc += wv.x * xv.x + wv.y * xv.y + wv.z * xv.z + wv.w * xv.w;
        }
        #pragma unroll
        for (int s = 16; s > 0; s >>= 1)
            acc += __shfl_down_sync(0xffffffff, acc, s);
        if (lane == 0) g_h[b * Hn + o] = acc + bd[o];
    }
}

// ------------------ K7: layernorm (K_B verbatim) ------------------
__global__ __launch_bounds__(256) void k_ln(const float* __restrict__ lw,
                                            const float* __restrict__ lb,
                                            float* __restrict__ out0) {
    __shared__ float red[256];
    int b = blockIdx.x, tid = threadIdx.x;
    float hv[3];
    #pragma unroll
    for (int j = 0; j < 3; j++) hv[j] = g_h[b * Hn + tid + 256 * j];

    red[tid] = hv[0] + hv[1] + hv[2];
    __syncthreads();
    for (int s = 128; s > 0; s >>= 1) {
        if (tid < s) red[tid] += red[tid + s];
        __syncthreads();
    }
    float u = red[0] / (float)Hn;
    __syncthreads();
    float vs = 0.f;
    #pragma unroll
    for (int j = 0; j < 3; j++) { float d = hv[j] - u; vs += d * d; }
    red[tid] = vs;
    __syncthreads();
    for (int s = 128; s > 0; s >>= 1) {
        if (tid < s) red[tid] += red[tid + s];
        __syncthreads();
    }
    float rstd = rsqrtf(red[0] / (float)Hn + 1e-12f);
    #pragma unroll
    for (int j = 0; j < 3; j++) {
        int o = tid + 256 * j;
        out0[b * Hn + o] = lw[o] * (hv[j] - u) * rstd + lb[o];
    }
}

// ------------------ launch ------------------
extern "C" void kernel_launch(void* const* d_in, const int* in_sizes, int n_in,
                              void* d_out, int out_size) {
    const float* hs = (const float*)d_in[0];
    const float* ad = (const float*)d_in[1];
    const float* am = (const float*)d_in[2];
    const float* Wt = (const float*)d_in[3];
    const float* Wa = (const float*)d_in[4];
    const float* tw = (const float*)d_in[5];
    const float* aw = (const float*)d_in[6];
    const float* fb = (const float*)d_in[7];
    const float* Wd = (const float*)d_in[8];
    const float* bd = (const float*)d_in[9];
    const float* lw = (const float*)d_in[10];
    const float* lb = (const float*)d_in[11];

    float* out    = (float*)d_out;
    float* out_h0 = out;
    float* out_ta = out + Bn * Hn;
    float* out_fa = out + Bn * Hn + (size_t)Bn * Sn * Sn;

    k_prep<<<104, 256>>>(Wt, Wa);
    k_proj<<<256, 256>>>(hs, ad);
    k_norm<<<1, 256>>>();
    k_scores<<<dim3(36, 32), 256>>>(tw, aw, fb, out_ta, out_fa);
    k_soft<<<32, 256>>>(am);
    k_av<<<dim3(32, 16), 192>>>(hs);
    k_dense<<<dim3(32, 8), 256>>>(hs, Wd, bd);
    k_ln<<<32, 256>>>(lw, lb, out_h0);
}